// round 1
// baseline (speedup 1.0000x reference)
#include <cuda_runtime.h>
#include <cstdint>
#include <cstddef>

#define B_   4
#define T_   448
#define U_   448
#define SKS_ 96
#define BKS_ 32
#define H_   96
#define V_   128
#define TT   32

typedef unsigned long long ull;

// Scratch (device globals: no allocation allowed)
__device__ float g_sh [B_ * T_ * H_];   // sh = s @ W_sh^T + b_sh
__device__ float g_rbh[B_ * U_ * H_];   // relu(b @ W_bh^T + b_bh)
__device__ float g_Wt [H_ * V_];        // W_out transposed to [h][v]

// ---- packed fp32x2 helpers (FFMA2 path, PTX-only per B300 docs) ----
__device__ __forceinline__ ull ffma2(ull a, ull b, ull c) {
    asm("fma.rn.f32x2 %0, %1, %2, %0;" : "+l"(c) : "l"(a), "l"(b));
    return c;
}
__device__ __forceinline__ ull fadd2(ull a, ull b) {
    ull r; asm("add.rn.f32x2 %0, %1, %2;" : "=l"(r) : "l"(a), "l"(b));
    return r;
}
__device__ __forceinline__ ull dup2(float x) {
    ull r; asm("mov.b64 %0, {%1, %1};" : "=l"(r) : "f"(x));
    return r;
}
__device__ __forceinline__ void unpack2(ull v, float& lo, float& hi) {
    asm("mov.b64 {%0, %1}, %2;" : "=f"(lo), "=f"(hi) : "l"(v));
}

// ============================================================================
// Kernel A: input projections. grid (B*T, 2), block 96.
//   y==0: sh[row][h] = dot(s[row], W_sh[h]) + b_sh[h]
//   y==1: rbh[row][h] = relu(dot(b[row], W_bh[h]) + b_bh[h])
// W staged in smem with padded pitch (97 / 33) so the h-indexed reads are
// bank-conflict-free ((h+k) mod 32 distinct across lanes).
// ============================================================================
__global__ __launch_bounds__(96) void proj_kernel(
    const float* __restrict__ s,   const float* __restrict__ bmat,
    const float* __restrict__ Wsh, const float* __restrict__ bsh,
    const float* __restrict__ Wbh, const float* __restrict__ bbh)
{
    __shared__ float sw[H_ * 97];
    __shared__ float srow[SKS_];
    const int row = blockIdx.x;
    const int h   = threadIdx.x;

    if (blockIdx.y == 0) {
        for (int i = h; i < H_ * SKS_; i += 96)
            sw[(i / SKS_) * 97 + (i % SKS_)] = Wsh[i];
        srow[h] = s[row * SKS_ + h];
        __syncthreads();
        float acc = bsh[h];
        #pragma unroll 8
        for (int k = 0; k < SKS_; k++)
            acc = fmaf(srow[k], sw[h * 97 + k], acc);
        g_sh[row * H_ + h] = acc;
    } else {
        for (int i = h; i < H_ * BKS_; i += 96)
            sw[(i / BKS_) * 33 + (i % BKS_)] = Wbh[i];
        if (h < BKS_) srow[h] = bmat[row * BKS_ + h];
        __syncthreads();
        float acc = bbh[h];
        #pragma unroll
        for (int k = 0; k < BKS_; k++)
            acc = fmaf(srow[k], sw[h * 33 + k], acc);
        g_rbh[row * H_ + h] = fmaxf(acc, 0.0f);
    }
}

// Tiny transpose so the main kernel can stage W coalesced & conflict-free.
__global__ void wtrans_kernel(const float* __restrict__ Wout) {
    g_Wt[blockIdx.x * V_ + threadIdx.x] = Wout[threadIdx.x * H_ + blockIdx.x];
}

// ============================================================================
// Main kernel. grid (T/TT, U, B) = (14, 448, 4), block 128, 74240 B dyn smem.
// CTA: one (b, u), TT=32 t-rows, full V=128.
// Thread (tg = tid>>4, vc = tid&15): 4 t-rows (tg*4..+3), 8 v as pairs
//   v = 32*p + 2*vc, p = 0..3  -> f32x2 accumulators, conflict-free LDS.64
//   on W (lane banks 2vc,2vc+1 cover 0..31), broadcast LDS.64 on z.
// Inner loop per h: 8 LDS.64 + 16 FFMA2  => FMA-pipe bound.
// Epilogue: bias add, log-softmax reduced over the 16 vc-lanes (shfl width 16),
// coalesced float2 stores. Single pass over the 411 MB output.
// ============================================================================
__global__ __launch_bounds__(128) void joiner_main(
    const float* __restrict__ bout, float* __restrict__ out)
{
    extern __shared__ char smem_raw[];
    ull*   zs2   = (ull*)  smem_raw;                                  // TT*H_ dup pairs
    float* sW    = (float*)(smem_raw + TT * H_ * 8);                  // [H_][V_]
    float* sBias = (float*)(smem_raw + TT * H_ * 8 + H_ * V_ * 4);    // [V_]

    const int tid = threadIdx.x;
    const int t0  = blockIdx.x * TT;
    const int u   = blockIdx.y;
    const int bz  = blockIdx.z;

    // Stage W_t (already [h][v]) coalesced, and the output bias.
    {
        const float4* src = (const float4*)g_Wt;
        float4*       dst = (float4*)sW;
        for (int i = tid; i < H_ * V_ / 4; i += 128) dst[i] = src[i];
        if (tid < V_ / 4) ((float4*)sBias)[tid] = ((const float4*)bout)[tid];
    }
    // z[t][h] = sh[b,t0+t,h] * rbh[b,u,h], stored pre-duplicated as f32x2.
    {
        const float* shp = g_sh  + (size_t)(bz * T_ + t0) * H_;
        const float* rbp = g_rbh + (size_t)(bz * U_ + u)  * H_;
        for (int i = tid; i < TT * H_; i += 128) {
            int t = i / H_, h = i - t * H_;
            zs2[i] = dup2(shp[t * H_ + h] * rbp[h]);
        }
    }
    __syncthreads();

    const int vc = tid & 15;
    const int tg = tid >> 4;

    ull acc[4][4];
    #pragma unroll
    for (int a = 0; a < 4; a++)
        #pragma unroll
        for (int p = 0; p < 4; p++) acc[a][p] = 0ULL;

    const ull*   zp = zs2 + tg * 4 * H_;
    const float* wp = sW + 2 * vc;

    #pragma unroll 4
    for (int h = 0; h < H_; h++) {
        ull w0 = *(const ull*)(wp + h * V_);
        ull w1 = *(const ull*)(wp + h * V_ + 32);
        ull w2 = *(const ull*)(wp + h * V_ + 64);
        ull w3 = *(const ull*)(wp + h * V_ + 96);
        ull z0 = zp[h];
        ull z1 = zp[H_ + h];
        ull z2 = zp[2 * H_ + h];
        ull z3 = zp[3 * H_ + h];
        acc[0][0] = ffma2(z0, w0, acc[0][0]);
        acc[0][1] = ffma2(z0, w1, acc[0][1]);
        acc[0][2] = ffma2(z0, w2, acc[0][2]);
        acc[0][3] = ffma2(z0, w3, acc[0][3]);
        acc[1][0] = ffma2(z1, w0, acc[1][0]);
        acc[1][1] = ffma2(z1, w1, acc[1][1]);
        acc[1][2] = ffma2(z1, w2, acc[1][2]);
        acc[1][3] = ffma2(z1, w3, acc[1][3]);
        acc[2][0] = ffma2(z2, w0, acc[2][0]);
        acc[2][1] = ffma2(z2, w1, acc[2][1]);
        acc[2][2] = ffma2(z2, w2, acc[2][2]);
        acc[2][3] = ffma2(z2, w3, acc[2][3]);
        acc[3][0] = ffma2(z3, w0, acc[3][0]);
        acc[3][1] = ffma2(z3, w1, acc[3][1]);
        acc[3][2] = ffma2(z3, w2, acc[3][2]);
        acc[3][3] = ffma2(z3, w3, acc[3][3]);
    }

    ull bb[4];
    #pragma unroll
    for (int p = 0; p < 4; p++)
        bb[p] = *(const ull*)(sBias + 2 * vc + 32 * p);

    #pragma unroll
    for (int tq = 0; tq < 4; tq++) {
        float v[8];
        #pragma unroll
        for (int p = 0; p < 4; p++) {
            ull a = fadd2(acc[tq][p], bb[p]);
            unpack2(a, v[2 * p], v[2 * p + 1]);
        }
        // log-softmax over the 128 logits of row t (16 lanes x 8 values)
        float m = v[0];
        #pragma unroll
        for (int i = 1; i < 8; i++) m = fmaxf(m, v[i]);
        #pragma unroll
        for (int off = 8; off >= 1; off >>= 1)
            m = fmaxf(m, __shfl_xor_sync(0xffffffffu, m, off, 16));
        float ssum = 0.0f;
        #pragma unroll
        for (int i = 0; i < 8; i++) ssum += __expf(v[i] - m);
        #pragma unroll
        for (int off = 8; off >= 1; off >>= 1)
            ssum += __shfl_xor_sync(0xffffffffu, ssum, off, 16);
        const float lse = m + __logf(ssum);

        const int t = t0 + tg * 4 + tq;
        float2* orow = (float2*)(out + (((size_t)bz * T_ + t) * U_ + u) * V_);
        #pragma unroll
        for (int p = 0; p < 4; p++) {
            float2 o;
            o.x = v[2 * p]     - lse;
            o.y = v[2 * p + 1] - lse;
            orow[16 * p + vc] = o;
        }
    }
}

static const int SMEM_MAIN = TT * H_ * 8 + H_ * V_ * 4 + V_ * 4;  // 74240 B

extern "C" void kernel_launch(void* const* d_in, const int* in_sizes, int n_in,
                              void* d_out, int out_size)
{
    (void)in_sizes; (void)n_in; (void)out_size;
    const float* s    = (const float*)d_in[0];
    const float* bmat = (const float*)d_in[1];
    const float* Wsh  = (const float*)d_in[2];
    const float* bsh  = (const float*)d_in[3];
    const float* Wbh  = (const float*)d_in[4];
    const float* bbh  = (const float*)d_in[5];
    const float* Wout = (const float*)d_in[6];
    const float* bout = (const float*)d_in[7];
    float* out = (float*)d_out;

    cudaFuncSetAttribute(joiner_main,
                         cudaFuncAttributeMaxDynamicSharedMemorySize, SMEM_MAIN);

    proj_kernel<<<dim3(B_ * T_, 2), 96>>>(s, bmat, Wsh, bsh, Wbh, bbh);
    wtrans_kernel<<<H_, V_>>>(Wout);
    joiner_main<<<dim3(T_ / TT, U_, B_), 128, SMEM_MAIN>>>(bout, out);
}

// round 5
// speedup vs baseline: 1.6065x; 1.6065x over previous
#include <cuda_runtime.h>
#include <cuda_bf16.h>
#include <cstdint>
#include <cstddef>

#define B_   4
#define T_   448
#define TPAD 512
#define U_   448
#define SKS_ 96
#define BKS_ 32
#define H_   96
#define V_   128
#define KP   112          // padded K: 96 (H) + 1 (bias) + pad -> 7 k-steps of 16
#define PITCH 240         // smem row pitch in bytes (120 bf16) -> conflict-free ldmatrix

// ---------------- device scratch ----------------
__device__ float g_sh [B_ * TPAD * H_];
__device__ float g_rbh[B_ * U_ * H_];

// ---------------- asm helpers ----------------
__device__ __forceinline__ uint32_t smem_u32(const void* p) {
    uint32_t a;
    asm("{ .reg .u64 t; cvta.to.shared.u64 t, %1; cvt.u32.u64 %0, t; }" : "=r"(a) : "l"(p));
    return a;
}
#define LDSM4(r, addr) \
    asm volatile("ldmatrix.sync.aligned.m8n8.x4.shared.b16 {%0,%1,%2,%3}, [%4];" \
        : "=r"((r)[0]), "=r"((r)[1]), "=r"((r)[2]), "=r"((r)[3]) : "r"(addr))

#define MMA16816(c, a, b0, b1) \
    asm volatile("mma.sync.aligned.m16n8k16.row.col.f32.bf16.bf16.f32 " \
        "{%0,%1,%2,%3}, {%4,%5,%6,%7}, {%8,%9}, {%0,%1,%2,%3};" \
        : "+f"((c)[0]), "+f"((c)[1]), "+f"((c)[2]), "+f"((c)[3]) \
        : "r"((a)[0]), "r"((a)[1]), "r"((a)[2]), "r"((a)[3]), "r"(b0), "r"(b1))

__device__ __forceinline__ uint32_t pack2bf(float a, float b) {
    __nv_bfloat162 h = __floats2bfloat162_rn(a, b);
    return *reinterpret_cast<uint32_t*>(&h);
}

// ============================================================================
// Input projections (same scheme as R1 winner, 8 rows/block).
// ============================================================================
__global__ __launch_bounds__(96) void proj8(
    const float* __restrict__ s,   const float* __restrict__ bmat,
    const float* __restrict__ Wsh, const float* __restrict__ bsh,
    const float* __restrict__ Wbh, const float* __restrict__ bbh)
{
    __shared__ float sw[H_ * 97];
    __shared__ float srow[8][97];
    const int h = threadIdx.x;

    if (blockIdx.y == 0) {
        for (int i = h; i < H_ * SKS_; i += 96)
            sw[(i / SKS_) * 97 + (i % SKS_)] = Wsh[i];
        const int base = blockIdx.x * 8;
        #pragma unroll
        for (int r = 0; r < 8; r++) {
            int row = base + r, b = row >> 9, t = row & 511;
            srow[r][h] = (t < T_) ? s[((size_t)b * T_ + t) * SKS_ + h] : 0.0f;
        }
        __syncthreads();
        float acc[8];
        const float bias = bsh[h];
        #pragma unroll
        for (int r = 0; r < 8; r++) acc[r] = bias;
        #pragma unroll 4
        for (int k = 0; k < SKS_; k++) {
            float w = sw[h * 97 + k];
            #pragma unroll
            for (int r = 0; r < 8; r++) acc[r] = fmaf(srow[r][k], w, acc[r]);
        }
        #pragma unroll
        for (int r = 0; r < 8; r++) g_sh[(size_t)(base + r) * H_ + h] = acc[r];
    } else {
        if (blockIdx.x >= (B_ * U_) / 8) return;
        for (int i = h; i < H_ * BKS_; i += 96)
            sw[(i / BKS_) * 33 + (i % BKS_)] = Wbh[i];
        const int base = blockIdx.x * 8;
        if (h < BKS_) {
            #pragma unroll
            for (int r = 0; r < 8; r++)
                srow[r][h] = bmat[(size_t)(base + r) * BKS_ + h];
        }
        __syncthreads();
        float acc[8];
        const float bias = bbh[h];
        #pragma unroll
        for (int r = 0; r < 8; r++) acc[r] = bias;
        #pragma unroll
        for (int k = 0; k < BKS_; k++) {
            float w = sw[h * 33 + k];
            #pragma unroll
            for (int r = 0; r < 8; r++) acc[r] = fmaf(srow[r][k], w, acc[r]);
        }
        #pragma unroll
        for (int r = 0; r < 8; r++) g_rbh[(size_t)(base + r) * H_ + h] = fmaxf(acc[r], 0.0f);
    }
}

// ============================================================================
// Persistent main kernel: 148 CTAs x 256 threads, legacy bf16 mma.sync,
// hi/lo 3-product split, fused log-softmax, coalesced-sector stores.
//
// Smem: A_hi/A_lo [128 x PITCH], B_hi/B_lo [128 x PITCH] (staged ONCE),
//       red [128][2] float2, rbh row [96].
// Warp layout: 8 warps; mg = wid>>1 -> rows mg*32..+31; ng = wid&1 -> cols ng*64..+63.
// ============================================================================
#define S_AHI 0
#define S_ALO 30720
#define S_BHI 61440
#define S_BLO 92160
#define S_RED 122880
#define S_RBH 124928
#define SMEM_MAIN 125440
#define NITEMS (4 * 4 * U_)   // ttile(4) * b(4) * u(448) = 7168

__global__ __launch_bounds__(256, 1) void joiner_hmma(
    const float* __restrict__ Wout, const float* __restrict__ bout,
    float* __restrict__ out)
{
    extern __shared__ __align__(16) char smem[];
    const uint32_t sb = smem_u32(smem);
    const int tid = threadIdx.x;
    const int wid = tid >> 5, lid = tid & 31;
    const int mg = wid >> 1, ng = wid & 1;
    const int n0 = ng * 64;
    const int q  = lid >> 2, qe = lid & 3;

    // ---- one-time: stage W_out hi/lo (bias folded at k==96) ----
    for (int idx = tid; idx < V_ * KP; idx += 256) {
        const int n = idx / KP, k = idx % KP;
        float w = (k < H_) ? Wout[n * H_ + k] : ((k == H_) ? bout[n] : 0.0f);
        __nv_bfloat16 hi = __float2bfloat16(w);
        float lo = w - __bfloat162float(hi);
        *(__nv_bfloat16*)(smem + S_BHI + n * PITCH + k * 2) = hi;
        *(__nv_bfloat16*)(smem + S_BLO + n * PITCH + k * 2) = __float2bfloat16(lo);
    }

    // ldmatrix lane address offsets
    const uint32_t aoff = (uint32_t)((lid & 15) * PITCH + (lid >> 4) * 16);
    const uint32_t boff = (uint32_t)(((lid & 7) + ((lid >> 4) << 3)) * PITCH + ((lid >> 3) & 1) * 16);
    const uint32_t sAh = sb + S_AHI + (uint32_t)(mg * 32 * PITCH) + aoff;
    const uint32_t sAl = sb + S_ALO + (uint32_t)(mg * 32 * PITCH) + aoff;
    const uint32_t sBh = sb + S_BHI + (uint32_t)(n0 * PITCH) + boff;
    const uint32_t sBl = sb + S_BLO + (uint32_t)(n0 * PITCH) + boff;

    float2* red = (float2*)(smem + S_RED);       // [128][2]
    float*  rbh = (float*)(smem + S_RBH);        // [96]

    for (int item = blockIdx.x; item < NITEMS; item += gridDim.x) {
        const int u  = item % U_;
        const int r2 = item / U_;
        const int t0 = (r2 & 3) * 128;
        const int bz = r2 >> 2;

        __syncthreads();   // previous item fully consumed (red + smem A)

        if (tid < H_) rbh[tid] = g_rbh[((size_t)bz * U_ + u) * H_ + tid];
        __syncthreads();

        // ---- A prep: z = sh * rbh, split to bf16 hi/lo in smem ----
        {
            const int row = tid >> 1;
            const int ks  = (tid & 1) * 56;
            const float4* shp = (const float4*)(g_sh + ((size_t)(bz * TPAD) + t0 + row) * H_);
            char* dh = smem + S_AHI + row * PITCH + ks * 2;
            char* dl = smem + S_ALO + row * PITCH + ks * 2;
            #pragma unroll
            for (int i = 0; i < 14; i++) {
                const int k0 = ks + 4 * i;
                float z0, z1, z2, z3;
                if (k0 < H_) {
                    float4 sv = shp[k0 >> 2];
                    z0 = sv.x * rbh[k0];     z1 = sv.y * rbh[k0 + 1];
                    z2 = sv.z * rbh[k0 + 2]; z3 = sv.w * rbh[k0 + 3];
                } else if (k0 == H_) { z0 = 1.0f; z1 = z2 = z3 = 0.0f; }
                else { z0 = z1 = z2 = z3 = 0.0f; }
                __nv_bfloat16 h0 = __float2bfloat16(z0), h1 = __float2bfloat16(z1);
                __nv_bfloat16 h2 = __float2bfloat16(z2), h3 = __float2bfloat16(z3);
                *(uint2*)(dh + 8 * i) = make_uint2(
                    pack2bf(__bfloat162float(h0), __bfloat162float(h1)),
                    pack2bf(__bfloat162float(h2), __bfloat162float(h3)));
                *(uint2*)(dl + 8 * i) = make_uint2(
                    pack2bf(z0 - __bfloat162float(h0), z1 - __bfloat162float(h1)),
                    pack2bf(z2 - __bfloat162float(h2), z3 - __bfloat162float(h3)));
            }
        }
        __syncthreads();

        // ---- MMA: 3 products (hi*hi, hi*lo, lo*hi) x 7 k-steps ----
        float acc[2][8][4];
        #pragma unroll
        for (int i = 0; i < 2; i++)
            #pragma unroll
            for (int j = 0; j < 8; j++)
                #pragma unroll
                for (int e = 0; e < 4; e++) acc[i][j][e] = 0.0f;

        #pragma unroll
        for (int p = 0; p < 3; p++) {
            const uint32_t Ab = (p == 2) ? sAl : sAh;
            const uint32_t Bb = (p == 1) ? sBl : sBh;
            #pragma unroll
            for (int s = 0; s < 7; s++) {
                uint32_t a[2][4], bq[4][4];
                LDSM4(a[0], Ab + s * 32);
                LDSM4(a[1], Ab + 16 * PITCH + s * 32);
                #pragma unroll
                for (int jj = 0; jj < 4; jj++)
                    LDSM4(bq[jj], Bb + jj * 16 * PITCH + s * 32);
                #pragma unroll
                for (int i = 0; i < 2; i++)
                    #pragma unroll
                    for (int j = 0; j < 8; j++)
                        MMA16816(acc[i][j], a[i], bq[j >> 1][(j & 1) * 2], bq[j >> 1][(j & 1) * 2 + 1]);
            }
        }

        // ---- epilogue: log-softmax over V=128 (two warps share each row) ----
        float mx[2][2], sm[2][2];
        #pragma unroll
        for (int i = 0; i < 2; i++)
            #pragma unroll
            for (int h = 0; h < 2; h++) {
                float m = -3.4e38f;
                #pragma unroll
                for (int j = 0; j < 8; j++) {
                    m = fmaxf(m, acc[i][j][2 * h]);
                    m = fmaxf(m, acc[i][j][2 * h + 1]);
                }
                m = fmaxf(m, __shfl_xor_sync(0xffffffffu, m, 1));
                m = fmaxf(m, __shfl_xor_sync(0xffffffffu, m, 2));
                float ss = 0.0f;
                #pragma unroll
                for (int j = 0; j < 8; j++)
                    ss += __expf(acc[i][j][2 * h] - m) + __expf(acc[i][j][2 * h + 1] - m);
                ss += __shfl_xor_sync(0xffffffffu, ss, 1);
                ss += __shfl_xor_sync(0xffffffffu, ss, 2);
                mx[i][h] = m; sm[i][h] = ss;
            }
        if (qe == 0) {
            #pragma unroll
            for (int i = 0; i < 2; i++)
                #pragma unroll
                for (int h = 0; h < 2; h++)
                    red[(mg * 32 + i * 16 + h * 8 + q) * 2 + ng] = make_float2(mx[i][h], sm[i][h]);
        }
        __syncthreads();

        #pragma unroll
        for (int i = 0; i < 2; i++)
            #pragma unroll
            for (int h = 0; h < 2; h++) {
                const int rloc = i * 16 + h * 8 + q;
                const int t = t0 + mg * 32 + rloc;
                if (t >= T_) continue;
                float2 o = red[(mg * 32 + rloc) * 2 + (ng ^ 1)];
                float M = fmaxf(mx[i][h], o.x);
                float S = sm[i][h] * __expf(mx[i][h] - M) + o.y * __expf(o.x - M);
                float lse = M + __logf(S);
                float2* op = (float2*)(out + (((size_t)bz * T_ + t) * U_ + u) * V_ + n0 + qe * 2);
                #pragma unroll
                for (int j = 0; j < 8; j++) {
                    float2 v;
                    v.x = acc[i][j][2 * h]     - lse;
                    v.y = acc[i][j][2 * h + 1] - lse;
                    op[4 * j] = v;
                }
            }
    }
}

extern "C" void kernel_launch(void* const* d_in, const int* in_sizes, int n_in,
                              void* d_out, int out_size)
{
    (void)in_sizes; (void)n_in; (void)out_size;
    const float* s    = (const float*)d_in[0];
    const float* bmat = (const float*)d_in[1];
    const float* Wsh  = (const float*)d_in[2];
    const float* bsh  = (const float*)d_in[3];
    const float* Wbh  = (const float*)d_in[4];
    const float* bbh  = (const float*)d_in[5];
    const float* Wout = (const float*)d_in[6];
    const float* bout = (const float*)d_in[7];
    float* out = (float*)d_out;

    cudaFuncSetAttribute(joiner_hmma,
                         cudaFuncAttributeMaxDynamicSharedMemorySize, SMEM_MAIN);

    proj8<<<dim3((B_ * TPAD) / 8, 2), 96>>>(s, bmat, Wsh, bsh, Wbh, bbh);
    joiner_hmma<<<148, 256, SMEM_MAIN>>>(Wout, bout, out);
}

// round 6
// speedup vs baseline: 2.0533x; 1.2781x over previous
#include <cuda_runtime.h>
#include <cuda_bf16.h>
#include <cstdint>
#include <cstddef>

#define B_   4
#define T_   448
#define TPAD 512
#define U_   448
#define SKS_ 96
#define BKS_ 32
#define H_   96
#define V_   128
#define KP   112          // padded K: 96 (H) + 1 (bias) + pad -> 7 k-steps of 16
#define PITCH 240         // smem B row pitch in bytes -> conflict-free ldmatrix

// ---------------- device scratch ----------------
__device__ float g_sh [B_ * TPAD * H_];
__device__ float g_rbh[B_ * U_ * H_];

// ---------------- asm helpers ----------------
__device__ __forceinline__ uint32_t smem_u32(const void* p) {
    uint32_t a;
    asm("{ .reg .u64 t; cvta.to.shared.u64 t, %1; cvt.u32.u64 %0, t; }" : "=r"(a) : "l"(p));
    return a;
}
#define LDSM4(r, addr) \
    asm volatile("ldmatrix.sync.aligned.m8n8.x4.shared.b16 {%0,%1,%2,%3}, [%4];" \
        : "=r"((r)[0]), "=r"((r)[1]), "=r"((r)[2]), "=r"((r)[3]) : "r"(addr))

#define MMA16816(c, a0, a1, a2, a3, b0, b1) \
    asm volatile("mma.sync.aligned.m16n8k16.row.col.f32.bf16.bf16.f32 " \
        "{%0,%1,%2,%3}, {%4,%5,%6,%7}, {%8,%9}, {%0,%1,%2,%3};" \
        : "+f"((c)[0]), "+f"((c)[1]), "+f"((c)[2]), "+f"((c)[3]) \
        : "r"(a0), "r"(a1), "r"(a2), "r"(a3), "r"(b0), "r"(b1))

__device__ __forceinline__ uint32_t pack2bf(float a, float b) {
    __nv_bfloat162 h = __floats2bfloat162_rn(a, b);
    return *reinterpret_cast<uint32_t*>(&h);
}
// bf16 hi/lo split of a float pair, both packed
__device__ __forceinline__ void split2(float z0, float z1, uint32_t& hi, uint32_t& lo) {
    __nv_bfloat162 h = __floats2bfloat162_rn(z0, z1);
    hi = *reinterpret_cast<uint32_t*>(&h);
    lo = pack2bf(z0 - __bfloat162float(h.x), z1 - __bfloat162float(h.y));
}

// ============================================================================
// Input projections (unchanged; ~5% of runtime).
// ============================================================================
__global__ __launch_bounds__(96) void proj8(
    const float* __restrict__ s,   const float* __restrict__ bmat,
    const float* __restrict__ Wsh, const float* __restrict__ bsh,
    const float* __restrict__ Wbh, const float* __restrict__ bbh)
{
    __shared__ float sw[H_ * 97];
    __shared__ float srow[8][97];
    const int h = threadIdx.x;

    if (blockIdx.y == 0) {
        for (int i = h; i < H_ * SKS_; i += 96)
            sw[(i / SKS_) * 97 + (i % SKS_)] = Wsh[i];
        const int base = blockIdx.x * 8;
        #pragma unroll
        for (int r = 0; r < 8; r++) {
            int row = base + r, b = row >> 9, t = row & 511;
            srow[r][h] = (t < T_) ? s[((size_t)b * T_ + t) * SKS_ + h] : 0.0f;
        }
        __syncthreads();
        float acc[8];
        const float bias = bsh[h];
        #pragma unroll
        for (int r = 0; r < 8; r++) acc[r] = bias;
        #pragma unroll 4
        for (int k = 0; k < SKS_; k++) {
            float w = sw[h * 97 + k];
            #pragma unroll
            for (int r = 0; r < 8; r++) acc[r] = fmaf(srow[r][k], w, acc[r]);
        }
        #pragma unroll
        for (int r = 0; r < 8; r++) g_sh[(size_t)(base + r) * H_ + h] = acc[r];
    } else {
        if (blockIdx.x >= (B_ * U_) / 8) return;
        for (int i = h; i < H_ * BKS_; i += 96)
            sw[(i / BKS_) * 33 + (i % BKS_)] = Wbh[i];
        const int base = blockIdx.x * 8;
        if (h < BKS_) {
            #pragma unroll
            for (int r = 0; r < 8; r++)
                srow[r][h] = bmat[(size_t)(base + r) * BKS_ + h];
        }
        __syncthreads();
        float acc[8];
        const float bias = bbh[h];
        #pragma unroll
        for (int r = 0; r < 8; r++) acc[r] = bias;
        #pragma unroll
        for (int k = 0; k < BKS_; k++) {
            float w = sw[h * 33 + k];
            #pragma unroll
            for (int r = 0; r < 8; r++) acc[r] = fmaf(srow[r][k], w, acc[r]);
        }
        #pragma unroll
        for (int r = 0; r < 8; r++) g_rbh[(size_t)(base + r) * H_ + h] = fmaxf(acc[r], 0.0f);
    }
}

// ============================================================================
// Persistent main kernel. 296 CTAs (2/SM) x 256 threads, A fragments built
// in registers (no A smem / LDSM), B hi/lo staged once per CTA.
// Warp: mg = wid>>1 -> rows mg*32..+31, ng = wid&1 -> cols ng*64..+63.
// ============================================================================
#define S_BHI 0
#define S_BLO 30720
#define S_RED 61440                 // [128][2] float2
#define S_RBH 63488                 // [96] float
#define SMEM_MAIN 64000
#define NITEMS (4 * 4 * U_)         // 7168
#define GRID_MAIN 296

__global__ __launch_bounds__(256, 2) void joiner_hmma(
    const float* __restrict__ Wout, const float* __restrict__ bout,
    float* __restrict__ out)
{
    extern __shared__ __align__(16) char smem[];
    const uint32_t sb = smem_u32(smem);
    const int tid = threadIdx.x;
    const int wid = tid >> 5, lid = tid & 31;
    const int mg = wid >> 1, ng = wid & 1;
    const int n0 = ng * 64;
    const int q  = lid >> 2, qe = lid & 3;

    // ---- one-time: stage W_out hi/lo (bias folded at k==96) ----
    for (int idx = tid; idx < V_ * KP; idx += 256) {
        const int n = idx / KP, k = idx % KP;
        float w = (k < H_) ? Wout[n * H_ + k] : ((k == H_) ? bout[n] : 0.0f);
        __nv_bfloat16 hi = __float2bfloat16(w);
        float lo = w - __bfloat162float(hi);
        *(__nv_bfloat16*)(smem + S_BHI + n * PITCH + k * 2) = hi;
        *(__nv_bfloat16*)(smem + S_BLO + n * PITCH + k * 2) = __float2bfloat16(lo);
    }

    // B ldmatrix lane addresses (same scheme that passed in R5)
    const uint32_t boff = (uint32_t)(((lid & 7) + ((lid >> 4) << 3)) * PITCH + ((lid >> 3) & 1) * 16);
    const uint32_t sBh = sb + S_BHI + (uint32_t)(n0 * PITCH) + boff;
    const uint32_t sBl = sb + S_BLO + (uint32_t)(n0 * PITCH) + boff;

    float2* red = (float2*)(smem + S_RED);
    float*  rbF = (float*)(smem + S_RBH);
    const float* rbL = rbF + 2 * qe;           // lane view: + 2e floats

    const uint32_t s6a = (qe == 0) ? pack2bf(1.0f, 0.0f) : 0u;   // k-step 6 A_hi const

    for (int item = blockIdx.x; item < NITEMS; item += GRID_MAIN) {
        const int u  = item % U_;
        const int r2 = item / U_;
        const int t0 = (r2 & 3) * 128;
        const int bz = r2 >> 2;

        __syncthreads();   // previous item's red/rbh fully consumed

        if (tid < H_) rbF[tid] = g_rbh[((size_t)bz * U_ + u) * H_ + tid];
        __syncthreads();

        // lane base into g_sh: row (t0 + mg*32 + q), col 2e
        const float* shL = g_sh + ((size_t)(bz * TPAD) + t0 + mg * 32 + q) * H_ + 2 * qe;

        float acc[2][8][4];
        #pragma unroll
        for (int i = 0; i < 2; i++)
            #pragma unroll
            for (int j = 0; j < 8; j++)
                #pragma unroll
                for (int e4 = 0; e4 < 4; e4++) acc[i][j][e4] = 0.0f;

        // ---- main k-steps 0..5: build A frags in regs, 3 products ----
        #pragma unroll
        for (int s = 0; s < 6; s++) {
            float2 rb0 = *(const float2*)(rbL + 16 * s);
            float2 rb1 = *(const float2*)(rbL + 16 * s + 8);
            uint32_t ah[2][4], al[2][4];
            #pragma unroll
            for (int i = 0; i < 2; i++) {
                #pragma unroll
                for (int rr = 0; rr < 2; rr++) {
                    const float* rp = shL + (i * 16 + rr * 8) * H_ + 16 * s;
                    float2 z0 = *(const float2*)(rp);
                    float2 z1 = *(const float2*)(rp + 8);
                    split2(z0.x * rb0.x, z0.y * rb0.y, ah[i][rr],     al[i][rr]);
                    split2(z1.x * rb1.x, z1.y * rb1.y, ah[i][rr + 2], al[i][rr + 2]);
                }
            }
            uint32_t bq[4][4];
            #pragma unroll
            for (int jj = 0; jj < 4; jj++)
                LDSM4(bq[jj], sBh + jj * 16 * PITCH + s * 32);
            #pragma unroll
            for (int i = 0; i < 2; i++)
                #pragma unroll
                for (int j = 0; j < 8; j++)
                    MMA16816(acc[i][j], ah[i][0], ah[i][1], ah[i][2], ah[i][3],
                             bq[j >> 1][(j & 1) * 2], bq[j >> 1][(j & 1) * 2 + 1]);
            #pragma unroll
            for (int i = 0; i < 2; i++)
                #pragma unroll
                for (int j = 0; j < 8; j++)
                    MMA16816(acc[i][j], al[i][0], al[i][1], al[i][2], al[i][3],
                             bq[j >> 1][(j & 1) * 2], bq[j >> 1][(j & 1) * 2 + 1]);
            #pragma unroll
            for (int jj = 0; jj < 4; jj++)
                LDSM4(bq[jj], sBl + jj * 16 * PITCH + s * 32);
            #pragma unroll
            for (int i = 0; i < 2; i++)
                #pragma unroll
                for (int j = 0; j < 8; j++)
                    MMA16816(acc[i][j], ah[i][0], ah[i][1], ah[i][2], ah[i][3],
                             bq[j >> 1][(j & 1) * 2], bq[j >> 1][(j & 1) * 2 + 1]);
        }
        // ---- k-step 6: bias slot; A_hi constant (1 at k=96), A_lo == 0 ----
        {
            uint32_t bq[4][4];
            #pragma unroll
            for (int jj = 0; jj < 4; jj++)
                LDSM4(bq[jj], sBh + jj * 16 * PITCH + 6 * 32);
            #pragma unroll
            for (int i = 0; i < 2; i++)
                #pragma unroll
                for (int j = 0; j < 8; j++)
                    MMA16816(acc[i][j], s6a, s6a, 0u, 0u,
                             bq[j >> 1][(j & 1) * 2], bq[j >> 1][(j & 1) * 2 + 1]);
            #pragma unroll
            for (int jj = 0; jj < 4; jj++)
                LDSM4(bq[jj], sBl + jj * 16 * PITCH + 6 * 32);
            #pragma unroll
            for (int i = 0; i < 2; i++)
                #pragma unroll
                for (int j = 0; j < 8; j++)
                    MMA16816(acc[i][j], s6a, s6a, 0u, 0u,
                             bq[j >> 1][(j & 1) * 2], bq[j >> 1][(j & 1) * 2 + 1]);
        }

        // ---- epilogue: log-softmax over V=128 (two warps share each row) ----
        float mx[2][2], sm[2][2];
        #pragma unroll
        for (int i = 0; i < 2; i++)
            #pragma unroll
            for (int h = 0; h < 2; h++) {
                float m = -3.4e38f;
                #pragma unroll
                for (int j = 0; j < 8; j++) {
                    m = fmaxf(m, acc[i][j][2 * h]);
                    m = fmaxf(m, acc[i][j][2 * h + 1]);
                }
                m = fmaxf(m, __shfl_xor_sync(0xffffffffu, m, 1));
                m = fmaxf(m, __shfl_xor_sync(0xffffffffu, m, 2));
                float ss = 0.0f;
                #pragma unroll
                for (int j = 0; j < 8; j++)
                    ss += __expf(acc[i][j][2 * h] - m) + __expf(acc[i][j][2 * h + 1] - m);
                ss += __shfl_xor_sync(0xffffffffu, ss, 1);
                ss += __shfl_xor_sync(0xffffffffu, ss, 2);
                mx[i][h] = m; sm[i][h] = ss;
            }
        if (qe == 0) {
            #pragma unroll
            for (int i = 0; i < 2; i++)
                #pragma unroll
                for (int h = 0; h < 2; h++)
                    red[(mg * 32 + i * 16 + h * 8 + q) * 2 + ng] = make_float2(mx[i][h], sm[i][h]);
        }
        __syncthreads();

        #pragma unroll
        for (int i = 0; i < 2; i++)
            #pragma unroll
            for (int h = 0; h < 2; h++) {
                const int rloc = i * 16 + h * 8 + q;
                const int t = t0 + mg * 32 + rloc;
                if (t >= T_) continue;
                float2 o = red[(mg * 32 + rloc) * 2 + (ng ^ 1)];
                float M = fmaxf(mx[i][h], o.x);
                float S = sm[i][h] * __expf(mx[i][h] - M) + o.y * __expf(o.x - M);
                float lse = M + __logf(S);
                float2* op = (float2*)(out + (((size_t)bz * T_ + t) * U_ + u) * V_ + n0 + qe * 2);
                #pragma unroll
                for (int j = 0; j < 8; j++) {
                    float2 v;
                    v.x = acc[i][j][2 * h]     - lse;
                    v.y = acc[i][j][2 * h + 1] - lse;
                    op[4 * j] = v;
                }
            }
    }
}

extern "C" void kernel_launch(void* const* d_in, const int* in_sizes, int n_in,
                              void* d_out, int out_size)
{
    (void)in_sizes; (void)n_in; (void)out_size;
    const float* s    = (const float*)d_in[0];
    const float* bmat = (const float*)d_in[1];
    const float* Wsh  = (const float*)d_in[2];
    const float* bsh  = (const float*)d_in[3];
    const float* Wbh  = (const float*)d_in[4];
    const float* bbh  = (const float*)d_in[5];
    const float* Wout = (const float*)d_in[6];
    const float* bout = (const float*)d_in[7];
    float* out = (float*)d_out;

    cudaFuncSetAttribute(joiner_hmma,
                         cudaFuncAttributeMaxDynamicSharedMemorySize, SMEM_MAIN);

    proj8<<<dim3((B_ * TPAD) / 8, 2), 96>>>(s, bmat, Wsh, bsh, Wbh, bbh);
    joiner_hmma<<<GRID_MAIN, 256, SMEM_MAIN>>>(Wout, bout, out);
}